// round 1
// baseline (speedup 1.0000x reference)
#include <cuda_runtime.h>
#include <cuda_bf16.h>
#include <math.h>

// ---------------- problem constants ----------------
#define NB   32          // batch
#define HH   32
#define WW   32
#define NPTS 32768       // NB*HH*WW
#define DIM  256
#define KC   1024        // codes
#define DECAY 0.99f
#define ONE_MINUS_DECAY 0.01f
#define EPS 1e-5f
#define BETA 0.25f
#define ZE_ELEMS (NB*DIM*HH*WW)   // 8388608

// output layout (float32, concatenated in reference return order)
#define OFF_ZQ    0
#define OFF_LOSS  8388608
#define OFF_IDX   8388609
#define OFF_EMB   8421377
#define OFF_CS    8683521
#define OFF_EMAW  8684545

// ---------------- device scratch ----------------
__device__ float g_flatz[NPTS * DIM];     // (N, D) transposed z_e
__device__ float g_enorm[KC];
__device__ int   g_idx[NPTS];
__device__ float g_counts[KC];
__device__ float g_dw[KC * DIM];
__device__ float g_loss;

// ---------------- K0: zero accumulators ----------------
__global__ void k_init() {
    int i = blockIdx.x * blockDim.x + threadIdx.x;
    if (i < KC * DIM) g_dw[i] = 0.0f;
    if (i < KC)       g_counts[i] = 0.0f;
    if (i == 0)       g_loss = 0.0f;
}

// ---------------- K1: transpose (B,D,H,W) -> (N,D) ----------------
// per-b: transpose (256, 1024) -> (1024, 256)
__global__ void k_transpose(const float* __restrict__ ze) {
    __shared__ float t[32][33];
    int b   = blockIdx.z;
    int hw0 = blockIdx.x * 32;
    int d0  = blockIdx.y * 32;
    int tx = threadIdx.x, ty = threadIdx.y;
    const float* src = ze + (size_t)b * DIM * (HH * WW);
    #pragma unroll
    for (int i = 0; i < 4; i++)
        t[ty + 8 * i][tx] = src[(d0 + ty + 8 * i) * (HH * WW) + hw0 + tx];
    __syncthreads();
    #pragma unroll
    for (int i = 0; i < 4; i++)
        g_flatz[((size_t)b * (HH * WW) + hw0 + ty + 8 * i) * DIM + d0 + tx] = t[tx][ty + 8 * i];
}

// ---------------- K1b: ||e_k||^2 ----------------
__global__ void k_enorm(const float* __restrict__ emb) {
    int k = blockIdx.x;             // 1024 blocks, 256 threads
    int t = threadIdx.x;
    float v = emb[k * DIM + t];
    float s = v * v;
    #pragma unroll
    for (int o = 16; o > 0; o >>= 1) s += __shfl_down_sync(0xffffffffu, s, o);
    __shared__ float ws[8];
    if ((t & 31) == 0) ws[t >> 5] = s;
    __syncthreads();
    if (t == 0) {
        float tot = 0.f;
        #pragma unroll
        for (int w = 0; w < 8; w++) tot += ws[w];
        g_enorm[k] = tot;
    }
}

// ---------------- K2: fused distance GEMM + argmin ----------------
// score(n,k) = ||e_k||^2 - 2 * dot(z_n, e_k)   (||z||^2 constant per row)
#define BM 64
#define BN 64
#define BK 64
#define PAD 65
__global__ __launch_bounds__(256) void k_argmin(const float* __restrict__ emb) {
    __shared__ float zs[BM][PAD];   // [m][d]
    __shared__ float es[BN][PAD];   // [k][d]
    __shared__ float rv[BM][16];
    __shared__ int   ri[BM][16];

    int tid = threadIdx.x;
    int tx = tid & 15;       // code quad
    int ty = tid >> 4;       // point quad
    int m0 = blockIdx.x * BM;

    float best[4] = {3.4e38f, 3.4e38f, 3.4e38f, 3.4e38f};
    int   bidx[4] = {0, 0, 0, 0};

    for (int kt = 0; kt < KC; kt += BN) {
        float acc[4][4];
        #pragma unroll
        for (int i = 0; i < 4; i++)
            #pragma unroll
            for (int j = 0; j < 4; j++) acc[i][j] = 0.0f;

        for (int dk = 0; dk < DIM; dk += BK) {
            // load 64x64 tiles (coalesced gmem, scalar smem stores w/ pad)
            #pragma unroll
            for (int s = 0; s < 16; s++) {
                int l = tid + s * 256;
                int r = l >> 6, c = l & 63;
                zs[r][c] = g_flatz[(size_t)(m0 + r) * DIM + dk + c];
                es[r][c] = emb[(size_t)(kt + r) * DIM + dk + c];
            }
            __syncthreads();
            #pragma unroll 8
            for (int dd = 0; dd < BK; dd++) {
                float a[4], b[4];
                #pragma unroll
                for (int i = 0; i < 4; i++) a[i] = zs[ty * 4 + i][dd];
                #pragma unroll
                for (int j = 0; j < 4; j++) b[j] = es[tx * 4 + j][dd];
                #pragma unroll
                for (int i = 0; i < 4; i++)
                    #pragma unroll
                    for (int j = 0; j < 4; j++) acc[i][j] = fmaf(a[i], b[j], acc[i][j]);
            }
            __syncthreads();
        }
        // epilogue: running argmin (ascending k -> strict '<' keeps lowest k on ties)
        #pragma unroll
        for (int j = 0; j < 4; j++) {
            int k = kt + tx * 4 + j;
            float e2 = g_enorm[k];
            #pragma unroll
            for (int i = 0; i < 4; i++) {
                float s = e2 - 2.0f * acc[i][j];
                if (s < best[i]) { best[i] = s; bidx[i] = k; }
            }
        }
    }

    #pragma unroll
    for (int i = 0; i < 4; i++) { rv[ty * 4 + i][tx] = best[i]; ri[ty * 4 + i][tx] = bidx[i]; }
    __syncthreads();
    if (tid < BM) {
        float bv = rv[tid][0]; int bi = ri[tid][0];
        #pragma unroll
        for (int t = 1; t < 16; t++) {
            float v = rv[tid][t]; int ix = ri[tid][t];
            if (v < bv || (v == bv && ix < bi)) { bv = v; bi = ix; }
        }
        g_idx[m0 + tid] = bi;
    }
}

// ---------------- K3: cluster counts ----------------
__global__ void k_counts() {
    int n = blockIdx.x * blockDim.x + threadIdx.x;
    if (n < NPTS) atomicAdd(&g_counts[g_idx[n]], 1.0f);
}

// ---------------- K4: dw scatter (segment sum of z) ----------------
__global__ void k_scatter() {
    int i = blockIdx.x * blockDim.x + threadIdx.x;
    if (i < NPTS * DIM) {
        int n = i >> 8, d = i & 255;
        atomicAdd(&g_dw[g_idx[n] * DIM + d], g_flatz[i]);
    }
}

// ---------------- K5: EMA update + new codebook ----------------
__global__ void k_finalize(const float* __restrict__ ema_cs,
                           const float* __restrict__ ema_w,
                           float* __restrict__ out) {
    int k = blockIdx.x;
    int d = threadIdx.x;
    float cs_new = DECAY * ema_cs[k] + ONE_MINUS_DECAY * g_counts[k];
    float w_new  = DECAY * ema_w[k * DIM + d] + ONE_MINUS_DECAY * g_dw[k * DIM + d];
    float e_new  = w_new / (cs_new + EPS);
    out[OFF_EMAW + k * DIM + d] = w_new;
    out[OFF_EMB  + k * DIM + d] = e_new;
    if (d == 0) out[OFF_CS + k] = cs_new;
}

// ---------------- K6: gather z_q (=z_q_st value) + commitment loss ----------------
__global__ void k_gather_loss(const float* __restrict__ ze, float* __restrict__ out) {
    int o = blockIdx.x * blockDim.x + threadIdx.x;   // (B,D,H,W) linear
    float sq = 0.0f;
    if (o < ZE_ELEMS) {
        int w = o & 31;
        int h = (o >> 5) & 31;
        int d = (o >> 10) & 255;
        int b = o >> 18;
        int n = (b << 10) + (h << 5) + w;
        float q = out[OFF_EMB + g_idx[n] * DIM + d];
        out[OFF_ZQ + o] = q;                  // z_q_st == z_q in value
        float diff = ze[o] - q;
        sq = diff * diff;
    }
    #pragma unroll
    for (int off = 16; off > 0; off >>= 1) sq += __shfl_down_sync(0xffffffffu, sq, off);
    __shared__ float ws[8];
    int t = threadIdx.x;
    if ((t & 31) == 0) ws[t >> 5] = sq;
    __syncthreads();
    if (t == 0) {
        float tot = 0.f;
        #pragma unroll
        for (int w2 = 0; w2 < 8; w2++) tot += ws[w2];
        atomicAdd(&g_loss, tot);
    }
}

// ---------------- K7: loss + indices outputs ----------------
__global__ void k_tail(float* __restrict__ out) {
    int i = blockIdx.x * blockDim.x + threadIdx.x;
    if (i < NPTS) out[OFF_IDX + i] = (float)g_idx[i];
    if (i == 0)   out[OFF_LOSS] = BETA * g_loss * (1.0f / (float)ZE_ELEMS);
}

// ---------------- launch ----------------
extern "C" void kernel_launch(void* const* d_in, const int* in_sizes, int n_in,
                              void* d_out, int out_size) {
    const float* z_e    = (const float*)d_in[0];
    const float* emb    = (const float*)d_in[1];
    const float* ema_cs = (const float*)d_in[2];
    const float* ema_w  = (const float*)d_in[3];
    float* out = (float*)d_out;

    k_init<<<(KC * DIM + 255) / 256, 256>>>();
    k_transpose<<<dim3(32, 8, 32), dim3(32, 8)>>>(z_e);
    k_enorm<<<KC, 256>>>(emb);
    k_argmin<<<NPTS / BM, 256>>>(emb);
    k_counts<<<(NPTS + 255) / 256, 256>>>();
    k_scatter<<<(NPTS * DIM + 255) / 256, 256>>>();
    k_finalize<<<KC, DIM>>>(ema_cs, ema_w, out);
    k_gather_loss<<<(ZE_ELEMS + 255) / 256, 256>>>(z_e, out);
    k_tail<<<(NPTS + 255) / 256, 256>>>(out);
}

// round 7
// speedup vs baseline: 1.1642x; 1.1642x over previous
#include <cuda_runtime.h>
#include <cuda_bf16.h>
#include <cstdint>
#include <math.h>

// ---------------- problem constants ----------------
#define NB   32
#define HH   32
#define WW   32
#define NPTS 32768
#define DIM  256
#define KC   1024
#define DECAY 0.99f
#define ONE_MINUS_DECAY 0.01f
#define EPS 1e-5f
#define BETA 0.25f
#define ZE_ELEMS (NB*DIM*HH*WW)

// output layout
#define OFF_ZQ    0
#define OFF_LOSS  8388608
#define OFF_IDX   8388609
#define OFF_EMB   8421377
#define OFF_CS    8683521
#define OFF_EMAW  8684545

// ---------------- GEMM config ----------------
#define K3    768          // 3*DIM : [A1|A1|A2] . [B1|B2|B1]
#define MT    128          // points per CTA
#define NTT   128          // codes per N tile
#define NTILES 8           // KC / NTT
#define KTILE 32           // k per smem tile (2 mma k-steps)
#define NKT   24           // K3 / KTILE
#define PITCH 80           // smem row pitch bytes (64B data, 80B stride -> LDSM conflict-free)
#define MARGIN 0.08f

// ---------------- device scratch ----------------
__device__ float g_flatz[NPTS * DIM];
__device__ float g_e2[KC];
__device__ int   g_idx[NPTS];
__device__ float g_counts[KC];
__device__ float g_dw[KC * DIM];
__device__ float g_loss;
__device__ __align__(16) __nv_bfloat16 g_A[(size_t)NPTS * K3];
__device__ __align__(16) __nv_bfloat16 g_B[(size_t)KC * K3];
__device__ int g_nflag;
__device__ int g_flaglist[NPTS];

__device__ __forceinline__ uint32_t smem_u32(const void* p) {
    uint32_t a;
    asm("{ .reg .u64 t; cvta.to.shared.u64 t, %1; cvt.u32.u64 %0, t; }" : "=r"(a) : "l"(p));
    return a;
}
__device__ __forceinline__ void ldsm_x4(uint32_t& r0, uint32_t& r1, uint32_t& r2, uint32_t& r3, uint32_t a) {
    asm volatile("ldmatrix.sync.aligned.m8n8.x4.shared.b16 {%0,%1,%2,%3}, [%4];"
                 : "=r"(r0), "=r"(r1), "=r"(r2), "=r"(r3) : "r"(a));
}
__device__ __forceinline__ void mma16816(float* c, uint32_t a0, uint32_t a1, uint32_t a2, uint32_t a3,
                                         uint32_t b0, uint32_t b1) {
    asm volatile("mma.sync.aligned.m16n8k16.row.col.f32.bf16.bf16.f32 "
                 "{%0,%1,%2,%3}, {%4,%5,%6,%7}, {%8,%9}, {%0,%1,%2,%3};"
                 : "+f"(c[0]), "+f"(c[1]), "+f"(c[2]), "+f"(c[3])
                 : "r"(a0), "r"(a1), "r"(a2), "r"(a3), "r"(b0), "r"(b1));
}

// ---------------- K0 ----------------
__global__ void k_init() {
    int i = blockIdx.x * blockDim.x + threadIdx.x;
    if (i < KC * DIM) g_dw[i] = 0.0f;
    if (i < KC)       g_counts[i] = 0.0f;
    if (i == 0)       { g_loss = 0.0f; g_nflag = 0; }
}

// ---------------- K1: transpose + bf16 split of z ----------------
__global__ void k_split_z(const float* __restrict__ ze) {
    __shared__ float t[32][33];
    int b = blockIdx.z, hw0 = blockIdx.x * 32, d0 = blockIdx.y * 32;
    int tx = threadIdx.x, ty = threadIdx.y;
    const float* src = ze + (size_t)b * DIM * (HH * WW);
    #pragma unroll
    for (int i = 0; i < 4; i++)
        t[ty + 8 * i][tx] = src[(d0 + ty + 8 * i) * (HH * WW) + hw0 + tx];
    __syncthreads();
    #pragma unroll
    for (int i = 0; i < 4; i++) {
        int n = b * (HH * WW) + hw0 + ty + 8 * i;
        int d = d0 + tx;
        float v = t[tx][ty + 8 * i];
        g_flatz[(size_t)n * DIM + d] = v;
        __nv_bfloat16 h1 = __float2bfloat16(v);
        __nv_bfloat16 h2 = __float2bfloat16(v - __bfloat162float(h1));
        size_t base = (size_t)n * K3 + d;
        g_A[base]       = h1;
        g_A[base + 256] = h1;
        g_A[base + 512] = h2;
    }
}

// ---------------- K1b: split emb + ||e||^2 ----------------
__global__ void k_split_emb(const float* __restrict__ emb) {
    int k = blockIdx.x, t = threadIdx.x;
    float v = emb[k * DIM + t];
    __nv_bfloat16 b1 = __float2bfloat16(v);
    __nv_bfloat16 b2 = __float2bfloat16(v - __bfloat162float(b1));
    size_t base = (size_t)k * K3 + t;
    g_B[base]       = b1;
    g_B[base + 256] = b2;
    g_B[base + 512] = b1;
    float s = v * v;
    #pragma unroll
    for (int o = 16; o > 0; o >>= 1) s += __shfl_down_sync(0xffffffffu, s, o);
    __shared__ float ws[8];
    if ((t & 31) == 0) ws[t >> 5] = s;
    __syncthreads();
    if (t == 0) {
        float tot = 0.f;
        #pragma unroll
        for (int w = 0; w < 8; w++) tot += ws[w];
        g_e2[k] = tot;
    }
}

// ---------------- K2: HMMA distance GEMM + fused argmin ----------------
// warp w owns rows [16w, 16w+16): argmin stays warp-local.
__global__ __launch_bounds__(256, 2) void k_argmin_mma() {
    __shared__ __align__(128) char Abuf[2][MT * PITCH];    // 2 x 10 KB
    __shared__ __align__(128) char Bbuf[2][NTT * PITCH];   // 2 x 10 KB
    __shared__ float e2s[NTT];

    int tid  = threadIdx.x;
    int lane = tid & 31;
    int w    = tid >> 5;
    int m0   = blockIdx.x * MT;

    // gmem load coords: thread covers rows lr and lr+64, 16B chunk lc
    int lr = tid >> 2, lc = tid & 3;
    const char* Ag0 = (const char*)g_A + ((size_t)(m0 + lr) * K3) * 2 + lc * 16;
    uint32_t stA = lr * PITCH + lc * 16;

    uint32_t sA = smem_u32(Abuf);
    uint32_t sB = smem_u32(Bbuf);

    // ldmatrix offsets
    // A: lanes 0-15 -> rows 0-15 @byte0 (k0-7 / k8-15 halves), lanes 16-31 -> @byte16
    uint32_t aoff = (w * 16 + (lane & 15)) * PITCH + (lane >> 4) * 16;
    // B ([n][k] row-major smem == col-major B, NON-trans ldmatrix):
    // lanes 0-7 -> n0-7 @k0-7, 8-15 -> n0-7 @k8-15, 16-23 -> n8-15 @k0-7, 24-31 -> n8-15 @k8-15
    uint32_t boff = ((lane & 7) + ((lane >> 4) << 3)) * PITCH + ((lane >> 3) & 1) * 16;

    float b1a = 3.4e38f, b2a = 3.4e38f; int i1a = 0;
    float b1b = 3.4e38f, b2b = 3.4e38f; int i1b = 0;

    for (int nt = 0; nt < NTILES; nt++) {
        if (tid < NTT) e2s[tid] = g_e2[nt * NTT + tid];
        const char* Bg0 = (const char*)g_B + ((size_t)(nt * NTT + lr) * K3) * 2 + lc * 16;

        // preload tile kt=0
        {
            uint4 va0 = *(const uint4*)(Ag0);
            uint4 va1 = *(const uint4*)(Ag0 + (size_t)64 * K3 * 2);
            uint4 vb0 = *(const uint4*)(Bg0);
            uint4 vb1 = *(const uint4*)(Bg0 + (size_t)64 * K3 * 2);
            *(uint4*)(Abuf[0] + stA) = va0;
            *(uint4*)(Abuf[0] + stA + 64 * PITCH) = va1;
            *(uint4*)(Bbuf[0] + stA) = vb0;
            *(uint4*)(Bbuf[0] + stA + 64 * PITCH) = vb1;
        }
        float acc[16][4];
        #pragma unroll
        for (int i = 0; i < 16; i++)
            #pragma unroll
            for (int j = 0; j < 4; j++) acc[i][j] = 0.0f;
        __syncthreads();

        #pragma unroll 1
        for (int kt = 0; kt < NKT; kt++) {
            int cur = kt & 1;
            uint4 va0, va1, vb0, vb1;
            if (kt < NKT - 1) {
                size_t go = (size_t)(kt + 1) * (KTILE * 2);
                va0 = *(const uint4*)(Ag0 + go);
                va1 = *(const uint4*)(Ag0 + go + (size_t)64 * K3 * 2);
                vb0 = *(const uint4*)(Bg0 + go);
                vb1 = *(const uint4*)(Bg0 + go + (size_t)64 * K3 * 2);
            }
            uint32_t abase = sA + cur * (MT * PITCH);
            uint32_t bbase = sB + cur * (NTT * PITCH);
            #pragma unroll
            for (int ks = 0; ks < 2; ks++) {
                uint32_t a0, a1, a2, a3;
                ldsm_x4(a0, a1, a2, a3, abase + aoff + ks * 32);
                #pragma unroll
                for (int nf2 = 0; nf2 < 8; nf2++) {   // FULL 128-code coverage (was 4: half!)
                    uint32_t r0, r1, r2, r3;
                    ldsm_x4(r0, r1, r2, r3, bbase + boff + nf2 * (16 * PITCH) + ks * 32);
                    mma16816(acc[nf2 * 2],     a0, a1, a2, a3, r0, r1);
                    mma16816(acc[nf2 * 2 + 1], a0, a1, a2, a3, r2, r3);
                }
            }
            if (kt < NKT - 1) {
                int nxt = 1 - cur;
                *(uint4*)(Abuf[nxt] + stA) = va0;
                *(uint4*)(Abuf[nxt] + stA + 64 * PITCH) = va1;
                *(uint4*)(Bbuf[nxt] + stA) = vb0;
                *(uint4*)(Bbuf[nxt] + stA + 64 * PITCH) = vb1;
            }
            __syncthreads();
        }

        // epilogue: scores + running argmin (k ascending everywhere)
        int c0 = (lane & 3) * 2;
        #pragma unroll
        for (int nf = 0; nf < 16; nf++) {
            int kbase = nt * NTT + nf * 8 + c0;
            float e20 = e2s[nf * 8 + c0];
            float e21 = e2s[nf * 8 + c0 + 1];
            float s;
            s = fmaf(-2.0f, acc[nf][0], e20);
            if (s < b1a) { b2a = b1a; b1a = s; i1a = kbase; } else if (s < b2a) b2a = s;
            s = fmaf(-2.0f, acc[nf][1], e21);
            if (s < b1a) { b2a = b1a; b1a = s; i1a = kbase + 1; } else if (s < b2a) b2a = s;
            s = fmaf(-2.0f, acc[nf][2], e20);
            if (s < b1b) { b2b = b1b; b1b = s; i1b = kbase; } else if (s < b2b) b2b = s;
            s = fmaf(-2.0f, acc[nf][3], e21);
            if (s < b1b) { b2b = b1b; b1b = s; i1b = kbase + 1; } else if (s < b2b) b2b = s;
        }
        __syncthreads();
    }

    // warp-local reduce across the 4 lanes sharing each row (shfl_xor 1,2)
    #pragma unroll
    for (int m = 1; m <= 2; m <<= 1) {
        float ob1 = __shfl_xor_sync(0xffffffffu, b1a, m);
        int   oi1 = __shfl_xor_sync(0xffffffffu, i1a, m);
        float ob2 = __shfl_xor_sync(0xffffffffu, b2a, m);
        if (ob1 < b1a || (ob1 == b1a && oi1 < i1a)) { b2a = fminf(b1a, ob2); b1a = ob1; i1a = oi1; }
        else b2a = fminf(b2a, ob1);
        ob1 = __shfl_xor_sync(0xffffffffu, b1b, m);
        oi1 = __shfl_xor_sync(0xffffffffu, i1b, m);
        ob2 = __shfl_xor_sync(0xffffffffu, b2b, m);
        if (ob1 < b1b || (ob1 == b1b && oi1 < i1b)) { b2b = fminf(b1b, ob2); b1b = ob1; i1b = oi1; }
        else b2b = fminf(b2b, ob1);
    }
    if ((lane & 3) == 0) {
        int r = lane >> 2;
        int ga = m0 + w * 16 + r;
        int gb = ga + 8;
        g_idx[ga] = i1a;
        g_idx[gb] = i1b;
        if (b2a - b1a < MARGIN) g_flaglist[atomicAdd(&g_nflag, 1)] = ga;
        if (b2b - b1b < MARGIN) g_flaglist[atomicAdd(&g_nflag, 1)] = gb;
    }
}

// ---------------- K2b: exact fp32 refinement for near-ties ----------------
__global__ void k_refine(const float* __restrict__ emb) {
    __shared__ float zrow[DIM];
    __shared__ float rbv[256];
    __shared__ int   rbi[256];
    int tid = threadIdx.x;
    int total = g_nflag;
    for (int it = blockIdx.x; it < total; it += gridDim.x) {
        int n = g_flaglist[it];
        zrow[tid] = g_flatz[(size_t)n * DIM + tid];
        __syncthreads();
        float best = 3.4e38f; int bi = 0;
        for (int kk = tid; kk < KC; kk += 256) {
            float sum = 0.0f;
            const float* er = emb + (size_t)kk * DIM;
            #pragma unroll 8
            for (int d = 0; d < DIM; d++) sum = fmaf(zrow[d], er[d], sum);
            float s = g_e2[kk] - 2.0f * sum;
            if (s < best) { best = s; bi = kk; }
        }
        rbv[tid] = best; rbi[tid] = bi;
        __syncthreads();
        for (int s = 128; s > 0; s >>= 1) {
            if (tid < s) {
                if (rbv[tid + s] < rbv[tid] ||
                    (rbv[tid + s] == rbv[tid] && rbi[tid + s] < rbi[tid])) {
                    rbv[tid] = rbv[tid + s]; rbi[tid] = rbi[tid + s];
                }
            }
            __syncthreads();
        }
        if (tid == 0) g_idx[n] = rbi[0];
        __syncthreads();
    }
}

// ---------------- K3..K7 ----------------
__global__ void k_counts() {
    int n = blockIdx.x * blockDim.x + threadIdx.x;
    if (n < NPTS) atomicAdd(&g_counts[g_idx[n]], 1.0f);
}
__global__ void k_scatter() {
    int i = blockIdx.x * blockDim.x + threadIdx.x;
    if (i < NPTS * DIM) {
        int n = i >> 8, d = i & 255;
        atomicAdd(&g_dw[g_idx[n] * DIM + d], g_flatz[i]);
    }
}
__global__ void k_finalize(const float* __restrict__ ema_cs,
                           const float* __restrict__ ema_w,
                           float* __restrict__ out) {
    int k = blockIdx.x, d = threadIdx.x;
    float cs_new = DECAY * ema_cs[k] + ONE_MINUS_DECAY * g_counts[k];
    float w_new  = DECAY * ema_w[k * DIM + d] + ONE_MINUS_DECAY * g_dw[k * DIM + d];
    out[OFF_EMAW + k * DIM + d] = w_new;
    out[OFF_EMB  + k * DIM + d] = w_new / (cs_new + EPS);
    if (d == 0) out[OFF_CS + k] = cs_new;
}
__global__ void k_gather_loss(const float* __restrict__ ze, float* __restrict__ out) {
    int o = blockIdx.x * blockDim.x + threadIdx.x;
    float sq = 0.0f;
    if (o < ZE_ELEMS) {
        int w = o & 31, h = (o >> 5) & 31, d = (o >> 10) & 255, b = o >> 18;
        int n = (b << 10) + (h << 5) + w;
        float q = out[OFF_EMB + g_idx[n] * DIM + d];
        out[OFF_ZQ + o] = q;
        float diff = ze[o] - q;
        sq = diff * diff;
    }
    #pragma unroll
    for (int off = 16; off > 0; off >>= 1) sq += __shfl_down_sync(0xffffffffu, sq, off);
    __shared__ float ws[8];
    int t = threadIdx.x;
    if ((t & 31) == 0) ws[t >> 5] = sq;
    __syncthreads();
    if (t == 0) {
        float tot = 0.f;
        #pragma unroll
        for (int w2 = 0; w2 < 8; w2++) tot += ws[w2];
        atomicAdd(&g_loss, tot);
    }
}
__global__ void k_tail(float* __restrict__ out) {
    int i = blockIdx.x * blockDim.x + threadIdx.x;
    if (i < NPTS) out[OFF_IDX + i] = (float)g_idx[i];
    if (i == 0)   out[OFF_LOSS] = BETA * g_loss * (1.0f / (float)ZE_ELEMS);
}

// ---------------- launch ----------------
extern "C" void kernel_launch(void* const* d_in, const int* in_sizes, int n_in,
                              void* d_out, int out_size) {
    const float* z_e    = (const float*)d_in[0];
    const float* emb    = (const float*)d_in[1];
    const float* ema_cs = (const float*)d_in[2];
    const float* ema_w  = (const float*)d_in[3];
    float* out = (float*)d_out;

    k_init<<<(KC * DIM + 255) / 256, 256>>>();
    k_split_z<<<dim3(32, 8, 32), dim3(32, 8)>>>(z_e);
    k_split_emb<<<KC, 256>>>(emb);
    k_argmin_mma<<<NPTS / MT, 256>>>();
    k_refine<<<128, 256>>>(emb);
    k_counts<<<(NPTS + 255) / 256, 256>>>();
    k_scatter<<<(NPTS * DIM + 255) / 256, 256>>>();
    k_finalize<<<KC, DIM>>>(ema_cs, ema_w, out);
    k_gather_loss<<<(ZE_ELEMS + 255) / 256, 256>>>(z_e, out);
    k_tail<<<(NPTS + 255) / 256, 256>>>(out);
}

// round 8
// speedup vs baseline: 1.2406x; 1.0656x over previous
#include <cuda_runtime.h>
#include <cuda_bf16.h>
#include <cstdint>
#include <math.h>

// ---------------- problem constants ----------------
#define NB   32
#define HH   32
#define WW   32
#define NPTS 32768
#define DIM  256
#define KC   1024
#define DECAY 0.99f
#define ONE_MINUS_DECAY 0.01f
#define EPS 1e-5f
#define BETA 0.25f
#define ZE_ELEMS (NB*DIM*HH*WW)

// output layout
#define OFF_ZQ    0
#define OFF_LOSS  8388608
#define OFF_IDX   8388609
#define OFF_EMB   8421377
#define OFF_CS    8683521
#define OFF_EMAW  8684545

// ---------------- GEMM config ----------------
#define K3    768          // 3*DIM : [A1|A1|A2] . [B1|B2|B1]
#define MT    128          // points per CTA
#define NTT   128          // codes per N tile
#define NTILES 8           // KC / NTT
#define KTILE 32           // k per smem tile (2 mma k-steps), 64B per row
#define NKT   24           // K3 / KTILE
#define PITCH 80           // smem row pitch bytes (64B data, 80B stride -> LDSM conflict-free)
#define ABUFB (MT * PITCH)   // 10240
#define MARGIN 0.08f

// ---------------- device scratch ----------------
__device__ float g_flatz[NPTS * DIM];
__device__ float g_e2[KC];
__device__ int   g_idx[NPTS];
__device__ float g_counts[KC];
__device__ float g_dw[KC * DIM];
__device__ float g_loss;
__device__ __align__(16) __nv_bfloat16 g_A[(size_t)NPTS * K3];
__device__ __align__(16) __nv_bfloat16 g_B[(size_t)KC * K3];
__device__ int g_nflag;
__device__ int g_flaglist[NPTS];

__device__ __forceinline__ uint32_t smem_u32(const void* p) {
    uint32_t a;
    asm("{ .reg .u64 t; cvta.to.shared.u64 t, %1; cvt.u32.u64 %0, t; }" : "=r"(a) : "l"(p));
    return a;
}
__device__ __forceinline__ void ldsm_x4(uint32_t& r0, uint32_t& r1, uint32_t& r2, uint32_t& r3, uint32_t a) {
    asm volatile("ldmatrix.sync.aligned.m8n8.x4.shared.b16 {%0,%1,%2,%3}, [%4];"
                 : "=r"(r0), "=r"(r1), "=r"(r2), "=r"(r3) : "r"(a));
}
__device__ __forceinline__ void mma16816(float* c, uint32_t a0, uint32_t a1, uint32_t a2, uint32_t a3,
                                         uint32_t b0, uint32_t b1) {
    asm volatile("mma.sync.aligned.m16n8k16.row.col.f32.bf16.bf16.f32 "
                 "{%0,%1,%2,%3}, {%4,%5,%6,%7}, {%8,%9}, {%0,%1,%2,%3};"
                 : "+f"(c[0]), "+f"(c[1]), "+f"(c[2]), "+f"(c[3])
                 : "r"(a0), "r"(a1), "r"(a2), "r"(a3), "r"(b0), "r"(b1));
}
#define CP_ASYNC16(sm, gm) asm volatile("cp.async.cg.shared.global [%0], [%1], 16;" :: "r"(sm), "l"(gm))
#define CP_COMMIT()        asm volatile("cp.async.commit_group;" ::: "memory")
#define CP_WAIT0()         asm volatile("cp.async.wait_group 0;" ::: "memory")

// ---------------- K0 ----------------
__global__ void k_init() {
    int i = blockIdx.x * blockDim.x + threadIdx.x;
    if (i < KC * DIM) g_dw[i] = 0.0f;
    if (i < KC)       g_counts[i] = 0.0f;
    if (i == 0)       { g_loss = 0.0f; g_nflag = 0; }
}

// ---------------- K1: transpose + bf16 split of z (vectorized stores) ----------------
__global__ void k_split_z(const float* __restrict__ ze) {
    __shared__ float t[32][33];
    int b = blockIdx.z, hw0 = blockIdx.x * 32, d0 = blockIdx.y * 32;
    int tx = threadIdx.x, ty = threadIdx.y;
    const float* src = ze + (size_t)b * DIM * (HH * WW);
    #pragma unroll
    for (int i = 0; i < 4; i++)
        t[ty + 8 * i][tx] = src[(d0 + ty + 8 * i) * (HH * WW) + hw0 + tx];  // t[d_local][hw_local]
    __syncthreads();
    int tid = ty * 32 + tx;
    if (tid < 128) {
        int hwl = tid >> 2, ch = tid & 3, dl0 = ch * 8;
        int n = b * (HH * WW) + hw0 + hwl;
        float v[8];
        #pragma unroll
        for (int j = 0; j < 8; j++) v[j] = t[dl0 + j][hwl];
        // flatz: 8 consecutive floats, two float4 stores
        float4* fz = (float4*)&g_flatz[(size_t)n * DIM + d0 + dl0];
        fz[0] = make_float4(v[0], v[1], v[2], v[3]);
        fz[1] = make_float4(v[4], v[5], v[6], v[7]);
        // bf16 hi/lo split, packed as bf16x2
        uint4 p1, p2;
        uint32_t* w1 = (uint32_t*)&p1;
        uint32_t* w2 = (uint32_t*)&p2;
        #pragma unroll
        for (int j2 = 0; j2 < 4; j2++) {
            __nv_bfloat16 a1 = __float2bfloat16(v[2 * j2]);
            __nv_bfloat16 b1 = __float2bfloat16(v[2 * j2 + 1]);
            __nv_bfloat16 a2 = __float2bfloat16(v[2 * j2]     - __bfloat162float(a1));
            __nv_bfloat16 b2 = __float2bfloat16(v[2 * j2 + 1] - __bfloat162float(b1));
            __nv_bfloat162 hp(a1, b1), lp(a2, b2);
            w1[j2] = *(uint32_t*)&hp;
            w2[j2] = *(uint32_t*)&lp;
        }
        uint4* abase = (uint4*)&g_A[(size_t)n * K3 + d0 + dl0];
        abase[0]  = p1;               // A1 @ +0
        abase[32] = p1;               // A1 dup @ +256 elems (512B)
        abase[64] = p2;               // A2 @ +512 elems
    }
}

// ---------------- K1b: split emb + ||e||^2 ----------------
__global__ void k_split_emb(const float* __restrict__ emb) {
    int k = blockIdx.x, t = threadIdx.x;
    float v = emb[k * DIM + t];
    __nv_bfloat16 b1 = __float2bfloat16(v);
    __nv_bfloat16 b2 = __float2bfloat16(v - __bfloat162float(b1));
    size_t base = (size_t)k * K3 + t;
    g_B[base]       = b1;
    g_B[base + 256] = b2;
    g_B[base + 512] = b1;
    float s = v * v;
    #pragma unroll
    for (int o = 16; o > 0; o >>= 1) s += __shfl_down_sync(0xffffffffu, s, o);
    __shared__ float ws[8];
    if ((t & 31) == 0) ws[t >> 5] = s;
    __syncthreads();
    if (t == 0) {
        float tot = 0.f;
        #pragma unroll
        for (int w = 0; w < 8; w++) tot += ws[w];
        g_e2[k] = tot;
    }
}

// ---------------- K2: HMMA distance GEMM + fused argmin ----------------
// 8 warps: warp = (mgrp 0-3) x (nhalf 0-1). Warp tile 32 rows x 64 cols.
__global__ __launch_bounds__(256, 2) void k_argmin_mma() {
    __shared__ __align__(128) char Abuf[2][ABUFB];
    __shared__ __align__(128) char Bbuf[2][ABUFB];
    __shared__ float e2s[NTT];
    __shared__ float sv1[2][MT], sv2[2][MT];
    __shared__ int   si[2][MT];

    int tid  = threadIdx.x;
    int lane = tid & 31;
    int w    = tid >> 5;
    int mgrp = w & 3, nhalf = w >> 2;
    int m0   = blockIdx.x * MT;
    int m0w  = mgrp * 32;

    // gmem<->smem copy coords: rows lr, lr+64; 16B chunk lc of the 64B row
    int lr = tid >> 2, lc = tid & 3;
    const char* Ag0 = (const char*)g_A + ((size_t)(m0 + lr) * K3) * 2 + lc * 16;
    uint32_t stA = lr * PITCH + lc * 16;

    uint32_t sA = smem_u32(Abuf);
    uint32_t sB = smem_u32(Bbuf);

    // ldmatrix fragment offsets
    uint32_t aoff0 = (m0w + (lane & 15)) * PITCH + (lane >> 4) * 16;              // +mf*16*PITCH
    uint32_t boff0 = (nhalf * 64 + (lane & 7) + ((lane >> 4) << 3)) * PITCH + ((lane >> 3) & 1) * 16; // +nf2*16*PITCH

    // argmin state: q = mf*2 + rhalf  (4 rows per thread)
    float B1[4] = {3.4e38f, 3.4e38f, 3.4e38f, 3.4e38f};
    float B2[4] = {3.4e38f, 3.4e38f, 3.4e38f, 3.4e38f};
    int   I1[4] = {0, 0, 0, 0};

    for (int nt = 0; nt < NTILES; nt++) {
        if (tid < NTT) e2s[tid] = g_e2[nt * NTT + tid];
        const char* Bg0 = (const char*)g_B + ((size_t)(nt * NTT + lr) * K3) * 2 + lc * 16;

        // preload kt=0 into buf0 via cp.async
        {
            CP_ASYNC16(sA + stA,                  Ag0);
            CP_ASYNC16(sA + stA + 64 * PITCH,     Ag0 + (size_t)64 * K3 * 2);
            CP_ASYNC16(sB + stA,                  Bg0);
            CP_ASYNC16(sB + stA + 64 * PITCH,     Bg0 + (size_t)64 * K3 * 2);
            CP_COMMIT();
        }
        float acc[2][8][4];
        #pragma unroll
        for (int i = 0; i < 2; i++)
            #pragma unroll
            for (int j = 0; j < 8; j++)
                #pragma unroll
                for (int x = 0; x < 4; x++) acc[i][j][x] = 0.0f;
        CP_WAIT0();
        __syncthreads();

        #pragma unroll 1
        for (int kt = 0; kt < NKT; kt++) {
            int cur = kt & 1;
            if (kt < NKT - 1) {
                int nxt = 1 - cur;
                size_t go = (size_t)(kt + 1) * (KTILE * 2);
                CP_ASYNC16(sA + nxt * ABUFB + stA,              Ag0 + go);
                CP_ASYNC16(sA + nxt * ABUFB + stA + 64 * PITCH, Ag0 + go + (size_t)64 * K3 * 2);
                CP_ASYNC16(sB + nxt * ABUFB + stA,              Bg0 + go);
                CP_ASYNC16(sB + nxt * ABUFB + stA + 64 * PITCH, Bg0 + go + (size_t)64 * K3 * 2);
                CP_COMMIT();
            }
            uint32_t abase = sA + cur * ABUFB + aoff0;
            uint32_t bbase = sB + cur * ABUFB + boff0;
            #pragma unroll
            for (int ks = 0; ks < 2; ks++) {
                uint32_t af[2][4];
                #pragma unroll
                for (int mf = 0; mf < 2; mf++)
                    ldsm_x4(af[mf][0], af[mf][1], af[mf][2], af[mf][3],
                            abase + mf * (16 * PITCH) + ks * 32);
                #pragma unroll
                for (int nf2 = 0; nf2 < 4; nf2++) {
                    uint32_t r0, r1, r2, r3;
                    ldsm_x4(r0, r1, r2, r3, bbase + nf2 * (16 * PITCH) + ks * 32);
                    #pragma unroll
                    for (int mf = 0; mf < 2; mf++) {
                        mma16816(acc[mf][nf2 * 2],     af[mf][0], af[mf][1], af[mf][2], af[mf][3], r0, r1);
                        mma16816(acc[mf][nf2 * 2 + 1], af[mf][0], af[mf][1], af[mf][2], af[mf][3], r2, r3);
                    }
                }
            }
            if (kt < NKT - 1) CP_WAIT0();
            __syncthreads();
        }

        // epilogue: scores + running argmin over this warp's 64-col slice
        int c0 = (lane & 3) * 2;
        #pragma unroll
        for (int mf = 0; mf < 2; mf++) {
            #pragma unroll
            for (int nf = 0; nf < 8; nf++) {
                int loc = nhalf * 64 + nf * 8 + c0;
                int k0 = nt * NTT + loc;
                float e20 = e2s[loc], e21 = e2s[loc + 1];
                float s;
                int qa = mf * 2, qb = mf * 2 + 1;
                s = fmaf(-2.0f, acc[mf][nf][0], e20);
                if (s < B1[qa]) { B2[qa] = B1[qa]; B1[qa] = s; I1[qa] = k0; } else if (s < B2[qa]) B2[qa] = s;
                s = fmaf(-2.0f, acc[mf][nf][1], e21);
                if (s < B1[qa]) { B2[qa] = B1[qa]; B1[qa] = s; I1[qa] = k0 + 1; } else if (s < B2[qa]) B2[qa] = s;
                s = fmaf(-2.0f, acc[mf][nf][2], e20);
                if (s < B1[qb]) { B2[qb] = B1[qb]; B1[qb] = s; I1[qb] = k0; } else if (s < B2[qb]) B2[qb] = s;
                s = fmaf(-2.0f, acc[mf][nf][3], e21);
                if (s < B1[qb]) { B2[qb] = B1[qb]; B1[qb] = s; I1[qb] = k0 + 1; } else if (s < B2[qb]) B2[qb] = s;
            }
        }
        __syncthreads();   // protect e2s for next tile
    }

    // intra-warp reduce across the 4 lanes (lane&3) sharing each row
    #pragma unroll
    for (int q = 0; q < 4; q++) {
        #pragma unroll
        for (int m = 1; m <= 2; m <<= 1) {
            float ob1 = __shfl_xor_sync(0xffffffffu, B1[q], m);
            int   oi1 = __shfl_xor_sync(0xffffffffu, I1[q], m);
            float ob2 = __shfl_xor_sync(0xffffffffu, B2[q], m);
            if (ob1 < B1[q] || (ob1 == B1[q] && oi1 < I1[q])) {
                B2[q] = fminf(B1[q], ob2); B1[q] = ob1; I1[q] = oi1;
            } else B2[q] = fminf(B2[q], ob1);
        }
    }
    if ((lane & 3) == 0) {
        int r = lane >> 2;
        #pragma unroll
        for (int mf = 0; mf < 2; mf++)
            #pragma unroll
            for (int rh = 0; rh < 2; rh++) {
                int q = mf * 2 + rh;
                int row = m0w + mf * 16 + r + rh * 8;
                sv1[nhalf][row] = B1[q];
                sv2[nhalf][row] = B2[q];
                si[nhalf][row]  = I1[q];
            }
    }
    __syncthreads();
    // final merge across warp-halves (disjoint n ranges)
    if (tid < MT) {
        float a1 = sv1[0][tid], a2 = sv2[0][tid]; int ai = si[0][tid];
        float c1 = sv1[1][tid], c2 = sv2[1][tid]; int ci = si[1][tid];
        float best, second; int bi;
        if (a1 < c1 || (a1 == c1 && ai < ci)) { best = a1; bi = ai; second = fminf(a2, c1); }
        else                                  { best = c1; bi = ci; second = fminf(c2, a1); }
        g_idx[m0 + tid] = bi;
        if (second - best < MARGIN) g_flaglist[atomicAdd(&g_nflag, 1)] = m0 + tid;
    }
}

// ---------------- K2b: exact fp32 refinement for near-ties ----------------
__global__ void k_refine(const float* __restrict__ emb) {
    __shared__ float zrow[DIM];
    __shared__ float rbv[256];
    __shared__ int   rbi[256];
    int tid = threadIdx.x;
    int total = g_nflag;
    for (int it = blockIdx.x; it < total; it += gridDim.x) {
        int n = g_flaglist[it];
        zrow[tid] = g_flatz[(size_t)n * DIM + tid];
        __syncthreads();
        float best = 3.4e38f; int bi = 0;
        for (int kk = tid; kk < KC; kk += 256) {
            float sum = 0.0f;
            const float* er = emb + (size_t)kk * DIM;
            #pragma unroll 8
            for (int d = 0; d < DIM; d++) sum = fmaf(zrow[d], er[d], sum);
            float s = g_e2[kk] - 2.0f * sum;
            if (s < best) { best = s; bi = kk; }
        }
        rbv[tid] = best; rbi[tid] = bi;
        __syncthreads();
        for (int s = 128; s > 0; s >>= 1) {
            if (tid < s) {
                if (rbv[tid + s] < rbv[tid] ||
                    (rbv[tid + s] == rbv[tid] && rbi[tid + s] < rbi[tid])) {
                    rbv[tid] = rbv[tid + s]; rbi[tid] = rbi[tid + s];
                }
            }
            __syncthreads();
        }
        if (tid == 0) g_idx[n] = rbi[0];
        __syncthreads();
    }
}

// ---------------- K3..K7 ----------------
__global__ void k_counts() {
    int n = blockIdx.x * blockDim.x + threadIdx.x;
    if (n < NPTS) atomicAdd(&g_counts[g_idx[n]], 1.0f);
}
__global__ void k_scatter() {
    int i = blockIdx.x * blockDim.x + threadIdx.x;   // NPTS*64 v4 chunks
    if (i < NPTS * 64) {
        int n = i >> 6, d4 = (i & 63) << 2;
        float4 v = *(const float4*)&g_flatz[(size_t)n * DIM + d4];
        float* dst = &g_dw[g_idx[n] * DIM + d4];
        asm volatile("red.global.add.v4.f32 [%0], {%1,%2,%3,%4};"
                     :: "l"(dst), "f"(v.x), "f"(v.y), "f"(v.z), "f"(v.w) : "memory");
    }
}
__global__ void k_finalize(const float* __restrict__ ema_cs,
                           const float* __restrict__ ema_w,
                           float* __restrict__ out) {
    int k = blockIdx.x, d = threadIdx.x;
    float cs_new = DECAY * ema_cs[k] + ONE_MINUS_DECAY * g_counts[k];
    float w_new  = DECAY * ema_w[k * DIM + d] + ONE_MINUS_DECAY * g_dw[k * DIM + d];
    out[OFF_EMAW + k * DIM + d] = w_new;
    out[OFF_EMB  + k * DIM + d] = w_new / (cs_new + EPS);
    if (d == 0) out[OFF_CS + k] = cs_new;
}
__global__ void k_gather_loss(const float* __restrict__ ze, float* __restrict__ out) {
    int o4 = (blockIdx.x * blockDim.x + threadIdx.x) << 2;
    float sq = 0.0f;
    if (o4 < ZE_ELEMS) {
        int w = o4 & 31, h = (o4 >> 5) & 31, d = (o4 >> 10) & 255, b = o4 >> 18;
        int nb = (b << 10) + (h << 5) + w;
        float4 z = *(const float4*)&ze[o4];
        float q0 = out[OFF_EMB + g_idx[nb]     * DIM + d];
        float q1 = out[OFF_EMB + g_idx[nb + 1] * DIM + d];
        float q2 = out[OFF_EMB + g_idx[nb + 2] * DIM + d];
        float q3 = out[OFF_EMB + g_idx[nb + 3] * DIM + d];
        *(float4*)&out[OFF_ZQ + o4] = make_float4(q0, q1, q2, q3);
        float d0 = z.x - q0, d1 = z.y - q1, d2 = z.z - q2, d3 = z.w - q3;
        sq = d0 * d0 + d1 * d1 + d2 * d2 + d3 * d3;
    }
    #pragma unroll
    for (int off = 16; off > 0; off >>= 1) sq += __shfl_down_sync(0xffffffffu, sq, off);
    __shared__ float ws[8];
    int t = threadIdx.x;
    if ((t & 31) == 0) ws[t >> 5] = sq;
    __syncthreads();
    if (t == 0) {
        float tot = 0.f;
        #pragma unroll
        for (int w2 = 0; w2 < 8; w2++) tot += ws[w2];
        atomicAdd(&g_loss, tot);
    }
}
__global__ void k_tail(float* __restrict__ out) {
    int i = blockIdx.x * blockDim.x + threadIdx.x;
    if (i < NPTS) out[OFF_IDX + i] = (float)g_idx[i];
    if (i == 0)   out[OFF_LOSS] = BETA * g_loss * (1.0f / (float)ZE_ELEMS);
}

// ---------------- launch ----------------
extern "C" void kernel_launch(void* const* d_in, const int* in_sizes, int n_in,
                              void* d_out, int out_size) {
    const float* z_e    = (const float*)d_in[0];
    const float* emb    = (const float*)d_in[1];
    const float* ema_cs = (const float*)d_in[2];
    const float* ema_w  = (const float*)d_in[3];
    float* out = (float*)d_out;

    k_init<<<(KC * DIM + 255) / 256, 256>>>();
    k_split_z<<<dim3(32, 8, 32), dim3(32, 8)>>>(z_e);
    k_split_emb<<<KC, 256>>>(emb);
    k_argmin_mma<<<NPTS / MT, 256>>>();
    k_refine<<<128, 256>>>(emb);
    k_counts<<<(NPTS + 255) / 256, 256>>>();
    k_scatter<<<(NPTS * 64 + 255) / 256, 256>>>();
    k_finalize<<<KC, DIM>>>(ema_cs, ema_w, out);
    k_gather_loss<<<(ZE_ELEMS / 4 + 255) / 256, 256>>>(z_e, out);
    k_tail<<<(NPTS + 255) / 256, 256>>>(out);
}